// round 4
// baseline (speedup 1.0000x reference)
#include <cuda_runtime.h>
#include <cuda_bf16.h>
#include <math.h>

#define NS 16
#define NV 8
#define HE 32
#define DD 40
#define WN 640
#define NE 160000
#define NN 10000
#define C110 0.57735026918962576451f
#define C111 0.70710678118654752440f
#define EPSV 1e-5f
#define EPT 128   // edges per block
#define NCH 20    // 2 branches x 10 chunks of 64 rows

typedef unsigned long long u64;

// ---------------- scratch ----------------
__device__ __align__(16) float g_q[NN * DD];
__device__ __align__(16) float g_W1T[2][32 * 32];     // [br][t*32+c] = w1[c][t]
__device__ __align__(16) float g_W2A[2][10 * 32 * 64]; // [br][ch][k][row] = w2[k][ch*64+row]
__device__ __align__(16) float g_b1[2][32];
__device__ __align__(16) float g_b2[2][WN];
__device__ __align__(16) float g_attn[NE];
__device__ __align__(16) float g_vedge[(size_t)NE * DD];
__device__ __align__(16) float g_num[NN * DD];
__device__ float g_stats[48];
__device__ int g_count[NN];
__device__ int g_off[NN + 1];
__device__ int g_cursor[NN];
__device__ int g_elist[NE];

// ---------------- packed f32x2 helpers ----------------
__device__ __forceinline__ u64 packf2(float lo, float hi) {
    u64 p; asm("mov.b64 %0, {%1, %2};" : "=l"(p) : "f"(lo), "f"(hi)); return p;
}
__device__ __forceinline__ u64 bcast2(float x) {
    u64 p; asm("mov.b64 %0, {%1, %1};" : "=l"(p) : "f"(x)); return p;
}
__device__ __forceinline__ void unpack2(u64 a, float& lo, float& hi) {
    asm("mov.b64 {%0, %1}, %2;" : "=f"(lo), "=f"(hi) : "l"(a));
}
__device__ __forceinline__ u64 mul2(u64 a, u64 b) {
    u64 r; asm("mul.rn.f32x2 %0, %1, %2;" : "=l"(r) : "l"(a), "l"(b)); return r;
}
__device__ __forceinline__ u64 add2(u64 a, u64 b) {
    u64 r; asm("add.rn.f32x2 %0, %1, %2;" : "=l"(r) : "l"(a), "l"(b)); return r;
}
__device__ __forceinline__ u64 fma2(u64 a, u64 b, u64 c) {
    u64 r; asm("fma.rn.f32x2 %0, %1, %2, %3;" : "=l"(r) : "l"(a), "l"(b), "l"(c)); return r;
}
__device__ __forceinline__ u64 neg2(u64 a) { return a ^ 0x8000000080000000ULL; }

// packed dot of 32 (for hidden layer)
__device__ __forceinline__ float dot32p(const u64 (&rh)[16], const float* __restrict__ row, float bias) {
    const ulonglong2* wp = (const ulonglong2*)row;
    u64 a0 = 0ULL, a1 = 0ULL, a2 = 0ULL, a3 = 0ULL;
#pragma unroll
    for (int q = 0; q < 4; q++) {
        ulonglong2 w0 = wp[2 * q];
        ulonglong2 w1 = wp[2 * q + 1];
        a0 = fma2(rh[4 * q + 0], w0.x, a0);
        a1 = fma2(rh[4 * q + 1], w0.y, a1);
        a2 = fma2(rh[4 * q + 2], w1.x, a2);
        a3 = fma2(rh[4 * q + 3], w1.y, a3);
    }
    a0 = add2(a0, a1); a2 = add2(a2, a3); a0 = add2(a0, a2);
    float lo, hi; unpack2(a0, lo, hi);
    return (lo + hi) + bias;
}

// ---------------- init ----------------
__global__ void init_kernel() {
    int i = blockIdx.x * blockDim.x + threadIdx.x;
    if (i < NN) g_count[i] = 0;
    if (i < 48) g_stats[i] = 0.f;
}

// ---------------- weight layout prep ----------------
__global__ void prep_kernel(const float* __restrict__ kw1, const float* __restrict__ kb1,
                            const float* __restrict__ kw2, const float* __restrict__ kb2,
                            const float* __restrict__ vw1, const float* __restrict__ vb1,
                            const float* __restrict__ vw2, const float* __restrict__ vb2) {
    const int PER = 20480 + 1024 + 32 + WN;  // 22176
    int id = blockIdx.x * blockDim.x + threadIdx.x;
    if (id >= 2 * PER) return;
    int b = id / PER, r = id % PER;
    const float* w1 = b ? vw1 : kw1;
    const float* w2 = b ? vw2 : kw2;
    const float* b1 = b ? vb1 : kb1;
    const float* b2 = b ? vb2 : kb2;
    if (r < 20480) {
        int ch = r >> 11;
        int within = r & 2047;
        int k = within >> 6;
        int row = within & 63;
        g_W2A[b][r] = w2[k * WN + ch * 64 + row];
    } else if (r < 20480 + 1024) {
        int q = r - 20480;
        int t = q >> 5, c = q & 31;
        g_W1T[b][q] = w1[c * 32 + t];
    } else if (r < 20480 + 1024 + 32) {
        g_b1[b][r - (20480 + 1024)] = b1[r - (20480 + 1024)];
    } else {
        g_b2[b][r - (20480 + 1024 + 32)] = b2[r - (20480 + 1024 + 32)];
    }
}

// ---------------- q projection ----------------
__global__ void qnode_kernel(const float* __restrict__ atom,
                             const float* __restrict__ Wqs, const float* __restrict__ Wqv) {
    __shared__ float sWs[256];
    __shared__ float sWv[64];
    int tid = threadIdx.x;
    if (tid < 256) sWs[tid] = Wqs[tid];
    if (tid < 64) sWv[tid] = Wqv[tid];
    __syncthreads();
    int n = blockIdx.x * 256 + tid;
    if (n >= NN) return;
    float xr[DD];
    const float4* p = (const float4*)(atom + (size_t)n * DD);
#pragma unroll
    for (int q = 0; q < 10; q++) {
        float4 t = p[q];
        xr[4 * q + 0] = t.x; xr[4 * q + 1] = t.y; xr[4 * q + 2] = t.z; xr[4 * q + 3] = t.w;
    }
    float qs[16];
#pragma unroll
    for (int o = 0; o < 16; o++) qs[o] = 0.f;
#pragma unroll
    for (int i = 0; i < 16; i++) {
        float xi = xr[i];
#pragma unroll
        for (int o = 0; o < 16; o++) qs[o] = fmaf(xi, sWs[i * 16 + o], qs[o]);
    }
    float qv[24];
#pragma unroll
    for (int o = 0; o < 24; o++) qv[o] = 0.f;
#pragma unroll
    for (int i = 0; i < 8; i++) {
#pragma unroll
        for (int o = 0; o < 8; o++) {
            float w = sWv[i * 8 + o];
            qv[3 * o + 0] = fmaf(xr[16 + 3 * i + 0], w, qv[3 * o + 0]);
            qv[3 * o + 1] = fmaf(xr[16 + 3 * i + 1], w, qv[3 * o + 1]);
            qv[3 * o + 2] = fmaf(xr[16 + 3 * i + 2], w, qv[3 * o + 2]);
        }
    }
    float* qp = g_q + (size_t)n * DD;
#pragma unroll
    for (int c = 0; c < 16; c++) qp[c] = qs[c];
#pragma unroll
    for (int c = 0; c < 24; c++) qp[16 + c] = qv[c];
}

// ---------------- main edge kernel: block GEMM + packed TP epilogue ----------------
// smem layout (floats unless noted):
//   sH   [2][32][128]   8192 f
//   sXs  [16][128]      2048 f
//   sXv  [24][128]      3072 f
//   sSh  [4][128]        512 f
//   sW1  [2][32][32]    2048 f
//   sB1  [64]             64 f
//   sA   [32][64]       2048 f
//   sB2p [64] u64        512 B
//   sC   [64][64] u64  32768 B
//   sSrc [128] int       512 B
//   sRed [512] f        2048 B
#define SMEM_TOTAL 107776

__global__ void __launch_bounds__(256, 2) edge_kernel(const float* __restrict__ atom,
                                                      const float* __restrict__ efeat,
                                                      const float* __restrict__ esh,
                                                      const int* __restrict__ eidx) {
    extern __shared__ float smem[];
    float* sH  = smem;                 // 8192
    float* sXs = sH + 8192;            // 2048
    float* sXv = sXs + 2048;           // 3072
    float* sSh = sXv + 3072;           // 512
    float* sW1 = sSh + 512;            // 2048
    float* sB1 = sW1 + 2048;           // 64
    float* sA  = sB1 + 64;             // 2048
    u64*  sB2p = (u64*)(sA + 2048);    // 64 u64
    u64*  sC   = sB2p + 64;            // 4096 u64
    int*  sSrc = (int*)(sC + 4096);    // 128
    float* sRed = (float*)(sSrc + 128);// 512

    const int tid = threadIdx.x;
    const int e0 = blockIdx.x * EPT;

    // ---- phase 0: W1 weights + per-edge node data ----
    for (int i = tid; i < 2048; i += 256) sW1[i] = ((const float*)g_W1T)[i];
    if (tid < 64) sB1[tid] = ((const float*)g_b1)[tid];
    if (tid < 128) {
        int e = e0 + tid;
        int dst = eidx[e], src = eidx[NE + e];
        sSrc[tid] = src;
        atomicAdd(&g_count[src], 1);
        const float4* p = (const float4*)(atom + (size_t)dst * DD);
#pragma unroll
        for (int q = 0; q < 4; q++) {
            float4 t = p[q];
            sXs[(4 * q + 0) * 128 + tid] = t.x;
            sXs[(4 * q + 1) * 128 + tid] = t.y;
            sXs[(4 * q + 2) * 128 + tid] = t.z;
            sXs[(4 * q + 3) * 128 + tid] = t.w;
        }
#pragma unroll
        for (int q = 0; q < 6; q++) {
            float4 t = p[4 + q];
            sXv[(4 * q + 0) * 128 + tid] = t.x;
            sXv[(4 * q + 1) * 128 + tid] = t.y;
            sXv[(4 * q + 2) * 128 + tid] = t.z;
            sXv[(4 * q + 3) * 128 + tid] = t.w;
        }
        float4 s4 = *(const float4*)(esh + (size_t)e * 4);
        sSh[0 * 128 + tid] = s4.x;
        sSh[1 * 128 + tid] = s4.y;
        sSh[2 * 128 + tid] = s4.z;
        sSh[3 * 128 + tid] = s4.w;
    }
    __syncthreads();

    // ---- phase 1: hidden layer for both branches ----
    {
        int e = e0 + (tid & 127);
        int br = tid >> 7;
        u64 efp[16];
        const ulonglong2* p = (const ulonglong2*)(efeat + (size_t)e * HE);
#pragma unroll
        for (int q = 0; q < 8; q++) {
            ulonglong2 t = p[q];
            efp[2 * q] = t.x; efp[2 * q + 1] = t.y;
        }
        const float* wbase = sW1 + br * 1024;
        const float* bbase = sB1 + br * 32;
        float* hbase = sH + br * 4096 + (tid & 127);
#pragma unroll 1
        for (int t2 = 0; t2 < 32; t2++) {
            float h = dot32p(efp, wbase + t2 * 32, bbase[t2]);
            hbase[t2 * 128] = fmaxf(h, 0.f);
        }
    }
    __syncthreads();

    // ---- GEMM + epilogue ----
    const int p_ = tid & 63;     // pair (epilogue)
    const int s_ = tid >> 6;     // sub 0..3 (epilogue output quarter)
    const int rowBase = (tid >> 4) * 4;  // GEMM row tile
    const int pairBase = (tid & 15) * 4; // GEMM pair tile

    const u64* ShU = (const u64*)sSh;
    const u64 shs2 = ShU[p_];
    const u64 sv02 = ShU[64 + p_];
    const u64 sv12 = ShU[128 + p_];
    const u64 sv22 = ShU[192 + p_];
    const u64 C110_2 = bcast2(C110);
    const u64 C111_2 = bcast2(C111);
    const u64* Xs = (const u64*)sXs;
    const u64* Xv = (const u64*)sXv;

    const float4* gW = (const float4*)g_W2A;  // [40960 floats] = 10240 float4
    const float* gB2 = (const float*)g_b2;    // [1280]

    float4 pre0 = gW[tid];
    float4 pre1 = gW[256 + tid];
    float preb = (tid < 64) ? gB2[tid] : 0.f;

    for (int br = 0; br < 2; br++) {
        const u64* sHb = (const u64*)sH + br * 2048;  // [32][64] u64
        u64 po_s[4], po_v[6];
#pragma unroll
        for (int j = 0; j < 4; j++) po_s[j] = 0ULL;
#pragma unroll
        for (int j = 0; j < 6; j++) po_v[j] = 0ULL;

        for (int ch = 0; ch < 10; ch++) {
            const int cc = br * 10 + ch;
            __syncthreads();
            ((float4*)sA)[tid] = pre0;
            ((float4*)sA)[256 + tid] = pre1;
            if (tid < 64) sB2p[tid] = bcast2(preb);
            __syncthreads();

            // GEMM: acc[4 rows][4 pairs]
            u64 acc[4][4];
#pragma unroll
            for (int r = 0; r < 4; r++)
#pragma unroll
                for (int c = 0; c < 4; c++) acc[r][c] = 0ULL;

#pragma unroll 8
            for (int k = 0; k < 32; k++) {
                float4 av = *(const float4*)(sA + k * 64 + rowBase);
                ulonglong2 bv0 = *(const ulonglong2*)(sHb + k * 64 + pairBase);
                ulonglong2 bv1 = *(const ulonglong2*)(sHb + k * 64 + pairBase + 2);
                u64 a0 = bcast2(av.x), a1 = bcast2(av.y), a2 = bcast2(av.z), a3 = bcast2(av.w);
                acc[0][0] = fma2(a0, bv0.x, acc[0][0]);
                acc[0][1] = fma2(a0, bv0.y, acc[0][1]);
                acc[0][2] = fma2(a0, bv1.x, acc[0][2]);
                acc[0][3] = fma2(a0, bv1.y, acc[0][3]);
                acc[1][0] = fma2(a1, bv0.x, acc[1][0]);
                acc[1][1] = fma2(a1, bv0.y, acc[1][1]);
                acc[1][2] = fma2(a1, bv1.x, acc[1][2]);
                acc[1][3] = fma2(a1, bv1.y, acc[1][3]);
                acc[2][0] = fma2(a2, bv0.x, acc[2][0]);
                acc[2][1] = fma2(a2, bv0.y, acc[2][1]);
                acc[2][2] = fma2(a2, bv1.x, acc[2][2]);
                acc[2][3] = fma2(a2, bv1.y, acc[2][3]);
                acc[3][0] = fma2(a3, bv0.x, acc[3][0]);
                acc[3][1] = fma2(a3, bv0.y, acc[3][1]);
                acc[3][2] = fma2(a3, bv1.x, acc[3][2]);
                acc[3][3] = fma2(a3, bv1.y, acc[3][3]);
            }
            // prefetch next chunk
            if (cc + 1 < NCH) {
                pre0 = gW[(cc + 1) * 512 + tid];
                pre1 = gW[(cc + 1) * 512 + 256 + tid];
                if (tid < 64) preb = gB2[(cc + 1) * 64 + tid];
            }
            // stage C chunk to smem
#pragma unroll
            for (int r = 0; r < 4; r++) {
                ulonglong2* cp = (ulonglong2*)(sC + (rowBase + r) * 64 + pairBase);
                cp[0] = make_ulonglong2(acc[r][0], acc[r][1]);
                cp[1] = make_ulonglong2(acc[r][2], acc[r][3]);
            }
            __syncthreads();

            // epilogue: fold chunk into per-pair accumulators
            if (ch < 6) {
                const int ibase = (ch < 4) ? ch * 4 : (ch - 4) * 4;
#pragma unroll
                for (int ii = 0; ii < 4; ii++) {
                    const int i = ibase + ii;
                    u64 ca;
                    if (ch < 4) {
                        ca = mul2(Xs[i * 64 + p_], shs2);
                    } else {
                        u64 d = mul2(Xv[(3 * i) * 64 + p_], sv02);
                        d = fma2(Xv[(3 * i + 1) * 64 + p_], sv12, d);
                        d = fma2(Xv[(3 * i + 2) * 64 + p_], sv22, d);
                        ca = mul2(d, C110_2);
                    }
#pragma unroll
                    for (int j = 0; j < 4; j++) {
                        const int r = ii * 16 + 4 * s_ + j;
                        u64 w = add2(sC[r * 64 + p_], sB2p[r]);
                        po_s[j] = fma2(w, ca, po_s[j]);
                    }
                }
            } else {
                const int ibase = (ch < 8) ? (ch - 6) * 8 : 0;
#pragma unroll
                for (int ii = 0; ii < 8; ii++) {
                    const int i = ibase + ii;
                    u64 c0, c1, c2;
                    if (ch < 8) {
                        u64 x = Xs[i * 64 + p_];
                        c0 = mul2(x, sv02); c1 = mul2(x, sv12); c2 = mul2(x, sv22);
                    } else if (ch == 8) {
                        c0 = mul2(Xv[(3 * i + 0) * 64 + p_], shs2);
                        c1 = mul2(Xv[(3 * i + 1) * 64 + p_], shs2);
                        c2 = mul2(Xv[(3 * i + 2) * 64 + p_], shs2);
                    } else {
                        u64 a0 = Xv[(3 * i + 0) * 64 + p_];
                        u64 a1 = Xv[(3 * i + 1) * 64 + p_];
                        u64 a2 = Xv[(3 * i + 2) * 64 + p_];
                        c0 = mul2(add2(mul2(a1, sv22), neg2(mul2(a2, sv12))), C111_2);
                        c1 = mul2(add2(mul2(a2, sv02), neg2(mul2(a0, sv22))), C111_2);
                        c2 = mul2(add2(mul2(a0, sv12), neg2(mul2(a1, sv02))), C111_2);
                    }
#pragma unroll
                    for (int j = 0; j < 2; j++) {
                        const int r = ii * 8 + 2 * s_ + j;
                        u64 w = add2(sC[r * 64 + p_], sB2p[r]);
                        po_v[3 * j + 0] = fma2(w, c0, po_v[3 * j + 0]);
                        po_v[3 * j + 1] = fma2(w, c1, po_v[3 * j + 1]);
                        po_v[3 * j + 2] = fma2(w, c2, po_v[3 * j + 2]);
                    }
                }
            }
        }

        // ---- retire ----
        if (br == 0) {
            const int srcA = sSrc[2 * p_], srcB = sSrc[2 * p_ + 1];
            const float* qA = g_q + (size_t)srcA * DD;
            const float* qB = g_q + (size_t)srcB * DD;
            float aA = 0.f, aB = 0.f;
#pragma unroll
            for (int j = 0; j < 4; j++) {
                float l, h; unpack2(po_s[j], l, h);
                const int c = 4 * s_ + j;
                aA = fmaf(l, qA[c], aA); aB = fmaf(h, qB[c], aB);
            }
#pragma unroll
            for (int j = 0; j < 6; j++) {
                float l, h; unpack2(po_v[j], l, h);
                const int c = 16 + 6 * s_ + j;
                aA = fmaf(l, qA[c], aA); aB = fmaf(h, qB[c], aB);
            }
            sRed[s_ * 64 + p_] = aA;
            sRed[256 + s_ * 64 + p_] = aB;
            __syncthreads();
            if (tid < 128) {
                const int pp = tid & 63, half = tid >> 6;
                const float* rb = sRed + half * 256;
                g_attn[e0 + 2 * pp + half] = rb[pp] + rb[64 + pp] + rb[128 + pp] + rb[192 + pp];
            }
        } else {
            const int ea = e0 + 2 * p_;
            float* va = g_vedge + (size_t)ea * DD;
            float* vb = va + DD;
#pragma unroll
            for (int j = 0; j < 4; j++) {
                float l, h; unpack2(po_s[j], l, h);
                va[4 * s_ + j] = l; vb[4 * s_ + j] = h;
            }
#pragma unroll
            for (int j = 0; j < 6; j++) {
                float l, h; unpack2(po_v[j], l, h);
                va[16 + 6 * s_ + j] = l; vb[16 + 6 * s_ + j] = h;
            }
        }
    }
}

// ---------------- CSR build: scan ----------------
__global__ void scan_kernel() {
    __shared__ int part[256];
    int tid = threadIdx.x;
    const int CH = (NN + 255) / 256;
    int beg = tid * CH;
    int end = beg + CH < NN ? beg + CH : NN;
    int s = 0;
    for (int i = beg; i < end; i++) s += g_count[i];
    part[tid] = s;
    __syncthreads();
    if (tid == 0) {
        int acc = 0;
        for (int i = 0; i < 256; i++) { int t = part[i]; part[i] = acc; acc += t; }
    }
    __syncthreads();
    int acc = part[tid];
    for (int i = beg; i < end; i++) {
        g_off[i] = acc;
        g_cursor[i] = acc;
        acc += g_count[i];
    }
    if (tid == 255) g_off[NN] = acc;
}

// ---------------- CSR build: scatter ----------------
__global__ void scatter_kernel(const int* __restrict__ eidx) {
    int e = blockIdx.x * 256 + threadIdx.x;
    int src = eidx[NE + e];
    int pos = atomicAdd(&g_cursor[src], 1);
    g_elist[pos] = e;
}

// ---------------- per-node softmax + aggregation + residual + stats ----------------
__global__ void gather_kernel(const float* __restrict__ atom) {
    __shared__ float sacc[48];
    int tid = threadIdx.x;
    if (tid < 48) sacc[tid] = 0.f;
    __syncthreads();
    int lane = tid & 31;
    int n = blockIdx.x * 4 + (tid >> 5);
    float x0 = 0.f, x1 = 0.f;
    {
        int beg = g_off[n], end = g_off[n + 1];
        float m = -INFINITY;
        for (int j = beg + lane; j < end; j += 32) m = fmaxf(m, g_attn[g_elist[j]]);
#pragma unroll
        for (int o = 16; o; o >>= 1) m = fmaxf(m, __shfl_xor_sync(~0u, m, o));
        if (!isfinite(m)) m = 0.f;
        float ds = 0.f;
        for (int j = beg + lane; j < end; j += 32) ds += expf(g_attn[g_elist[j]] - m);
#pragma unroll
        for (int o = 16; o; o >>= 1) ds += __shfl_xor_sync(~0u, ds, o);
        float a0 = 0.f, a1 = 0.f;
        for (int j = beg; j < end; j++) {
            int e = g_elist[j];
            float ev = expf(g_attn[e] - m);
            const float* vp = g_vedge + (size_t)e * DD;
            a0 = fmaf(ev, vp[lane], a0);
            if (lane < 8) a1 = fmaf(ev, vp[32 + lane], a1);
        }
        float inv = (ds != 0.f) ? 1.f / ds : 0.f;
        x0 = atom[(size_t)n * DD + lane] + a0 * inv;
        g_num[(size_t)n * DD + lane] = x0;
        if (lane < 8) {
            x1 = atom[(size_t)n * DD + 32 + lane] + a1 * inv;
            g_num[(size_t)n * DD + 32 + lane] = x1;
        }
    }
    if (lane < 16) {
        atomicAdd(&sacc[lane], x0);
        atomicAdd(&sacc[16 + lane], x0 * x0);
    } else {
        atomicAdd(&sacc[32 + (lane - 16) / 3], x0 * x0);
    }
    if (lane < 8) atomicAdd(&sacc[32 + (lane + 16) / 3], x1 * x1);
    __syncthreads();
    if (tid < 48) atomicAdd(&g_stats[tid], sacc[tid]);
}

// ---------------- finalize: batchnorm + write ----------------
__global__ void finalB_kernel(float* __restrict__ out,
                              const float* __restrict__ ws, const float* __restrict__ bs,
                              const float* __restrict__ wv) {
    int n = blockIdx.x * 256 + threadIdx.x;
    if (n >= NN) return;
    const float invN = 1.f / (float)NN;
#pragma unroll
    for (int c = 0; c < 16; c++) {
        float mu = g_stats[c] * invN;
        float var = g_stats[16 + c] * invN - mu * mu;
        float x = g_num[(size_t)n * DD + c];
        out[(size_t)n * DD + c] = (x - mu) / sqrtf(var + EPSV) * ws[c] + bs[c];
    }
#pragma unroll
    for (int i = 0; i < 8; i++) {
        float norm = g_stats[32 + i] * (invN * (1.f / 3.f));
        float sc = wv[i] / sqrtf(norm + EPSV);
#pragma unroll
        for (int d = 0; d < 3; d++) {
            float x = g_num[(size_t)n * DD + 16 + 3 * i + d];
            out[(size_t)n * DD + 16 + 3 * i + d] = x * sc;
        }
    }
}

// ---------------- launch ----------------
extern "C" void kernel_launch(void* const* d_in, const int* in_sizes, int n_in,
                              void* d_out, int out_size) {
    const float* atom  = (const float*)d_in[0];
    const float* efeat = (const float*)d_in[1];
    const float* esh   = (const float*)d_in[2];
    const float* Wqs   = (const float*)d_in[3];
    const float* Wqv   = (const float*)d_in[4];
    const float* kw1   = (const float*)d_in[5];
    const float* kb1   = (const float*)d_in[6];
    const float* kw2   = (const float*)d_in[7];
    const float* kb2   = (const float*)d_in[8];
    const float* vw1   = (const float*)d_in[9];
    const float* vb1   = (const float*)d_in[10];
    const float* vw2   = (const float*)d_in[11];
    const float* vb2   = (const float*)d_in[12];
    const float* bnws  = (const float*)d_in[13];
    const float* bnbs  = (const float*)d_in[14];
    const float* bnwv  = (const float*)d_in[15];
    const int*   eidx  = (const int*)d_in[16];
    float* out = (float*)d_out;

    cudaFuncSetAttribute(edge_kernel, cudaFuncAttributeMaxDynamicSharedMemorySize, SMEM_TOTAL);

    init_kernel<<<(NN + 255) / 256, 256>>>();
    prep_kernel<<<(2 * 22176 + 255) / 256, 256>>>(kw1, kb1, kw2, kb2, vw1, vb1, vw2, vb2);
    qnode_kernel<<<(NN + 255) / 256, 256>>>(atom, Wqs, Wqv);
    edge_kernel<<<NE / EPT, 256, SMEM_TOTAL>>>(atom, efeat, esh, eidx);
    scan_kernel<<<1, 256>>>();
    scatter_kernel<<<NE / 256, 256>>>(eidx);
    gather_kernel<<<NN / 4, 128>>>(atom);
    finalB_kernel<<<(NN + 255) / 256, 256>>>(out, bnws, bnbs, bnwv);
    cudaMemcpyAsync(out + NN * DD, efeat, (size_t)NE * HE * sizeof(float),
                    cudaMemcpyDeviceToDevice);
}

// round 5
// speedup vs baseline: 1.0689x; 1.0689x over previous
#include <cuda_runtime.h>
#include <cuda_bf16.h>
#include <math.h>

#define NS 16
#define NV 8
#define HE 32
#define DD 40
#define WN 640
#define NE 160000
#define NN 10000
#define C110 0.57735026918962576451f
#define C111 0.70710678118654752440f
#define EPSV 1e-5f

typedef unsigned long long u64;

// ---------------- scratch ----------------
__device__ __align__(16) float g_q[NN * DD];
__device__ __align__(16) float g_W1T[2][32 * 32];
__device__ __align__(16) float g_W2T[2][WN * 32];
__device__ __align__(16) float g_b1[2][32];
__device__ __align__(16) float g_b2[2][WN];
__device__ __align__(16) float g_attn[NE];
__device__ __align__(16) float g_vedge[(size_t)NE * DD];
__device__ __align__(16) float g_num[NN * DD];
__device__ float g_stats[48];
__device__ int g_count[NN];
__device__ int g_off[NN + 1];
__device__ int g_cursor[NN];
__device__ int g_elist[NE];

// ---------------- packed helpers ----------------
__device__ __forceinline__ u64 packf2(float lo, float hi) {
    u64 p; asm("mov.b64 %0, {%1, %2};" : "=l"(p) : "f"(lo), "f"(hi)); return p;
}
__device__ __forceinline__ u64 fma2(u64 a, u64 b, u64 c) {
    u64 r; asm("fma.rn.f32x2 %0, %1, %2, %3;" : "=l"(r) : "l"(a), "l"(b), "l"(c)); return r;
}
__device__ __forceinline__ u64 add2(u64 a, u64 b) {
    u64 r; asm("add.rn.f32x2 %0, %1, %2;" : "=l"(r) : "l"(a), "l"(b)); return r;
}
__device__ __forceinline__ void unpack2(u64 a, float& lo, float& hi) {
    asm("mov.b64 {%0, %1}, %2;" : "=f"(lo), "=f"(hi) : "l"(a));
}

// dual dot: one weight-row load feeds two packed dot products
__device__ __forceinline__ void dot2(const u64 (&ra)[16], const u64 (&rb)[16],
                                     const float* __restrict__ row, float bias,
                                     float& da, float& db) {
    const ulonglong2* wp = (const ulonglong2*)row;
    u64 a0 = 0ULL, a1 = 0ULL, a2 = 0ULL, a3 = 0ULL;
    u64 b0 = 0ULL, b1 = 0ULL, b2 = 0ULL, b3 = 0ULL;
#pragma unroll
    for (int q = 0; q < 4; q++) {
        ulonglong2 w0 = wp[2 * q];
        ulonglong2 w1 = wp[2 * q + 1];
        a0 = fma2(ra[4 * q + 0], w0.x, a0);
        b0 = fma2(rb[4 * q + 0], w0.x, b0);
        a1 = fma2(ra[4 * q + 1], w0.y, a1);
        b1 = fma2(rb[4 * q + 1], w0.y, b1);
        a2 = fma2(ra[4 * q + 2], w1.x, a2);
        b2 = fma2(rb[4 * q + 2], w1.x, b2);
        a3 = fma2(ra[4 * q + 3], w1.y, a3);
        b3 = fma2(rb[4 * q + 3], w1.y, b3);
    }
    a0 = add2(a0, a1); a2 = add2(a2, a3); a0 = add2(a0, a2);
    b0 = add2(b0, b1); b2 = add2(b2, b3); b0 = add2(b0, b2);
    float alo, ahi, blo, bhi;
    unpack2(a0, alo, ahi);
    unpack2(b0, blo, bhi);
    da = (alo + ahi) + bias;
    db = (blo + bhi) + bias;
}

// ---------------- init ----------------
__global__ void init_kernel() {
    int i = blockIdx.x * blockDim.x + threadIdx.x;
    if (i < NN) g_count[i] = 0;
    if (i < 48) g_stats[i] = 0.f;
}

// ---------------- weight transpose / copy ----------------
__global__ void prep_kernel(const float* __restrict__ kw1, const float* __restrict__ kb1,
                            const float* __restrict__ kw2, const float* __restrict__ kb2,
                            const float* __restrict__ vw1, const float* __restrict__ vb1,
                            const float* __restrict__ vw2, const float* __restrict__ vb2) {
    const int PER = WN * 32 + 1024 + 32 + WN;
    int id = blockIdx.x * blockDim.x + threadIdx.x;
    if (id >= 2 * PER) return;
    int b = id / PER, r = id % PER;
    const float* w1 = b ? vw1 : kw1;
    const float* w2 = b ? vw2 : kw2;
    const float* b1 = b ? vb1 : kb1;
    const float* b2 = b ? vb2 : kb2;
    if (r < WN * 32) {
        int j = r >> 5, t = r & 31;
        g_W2T[b][r] = w2[t * WN + j];
    } else if (r < WN * 32 + 1024) {
        int q = r - WN * 32;
        int t = q >> 5, c = q & 31;
        g_W1T[b][q] = w1[c * 32 + t];
    } else if (r < WN * 32 + 1024 + 32) {
        g_b1[b][r - (WN * 32 + 1024)] = b1[r - (WN * 32 + 1024)];
    } else {
        g_b2[b][r - (WN * 32 + 1024 + 32)] = b2[r - (WN * 32 + 1024 + 32)];
    }
}

// ---------------- q projection ----------------
__global__ void qnode_kernel(const float* __restrict__ atom,
                             const float* __restrict__ Wqs, const float* __restrict__ Wqv) {
    __shared__ float sWs[256];
    __shared__ float sWv[64];
    int tid = threadIdx.x;
    if (tid < 256) sWs[tid] = Wqs[tid];
    if (tid < 64) sWv[tid] = Wqv[tid];
    __syncthreads();
    int n = blockIdx.x * 256 + tid;
    if (n >= NN) return;
    float xr[DD];
    const float4* p = (const float4*)(atom + (size_t)n * DD);
#pragma unroll
    for (int q = 0; q < 10; q++) {
        float4 t = p[q];
        xr[4 * q + 0] = t.x; xr[4 * q + 1] = t.y; xr[4 * q + 2] = t.z; xr[4 * q + 3] = t.w;
    }
    float qs[16];
#pragma unroll
    for (int o = 0; o < 16; o++) qs[o] = 0.f;
#pragma unroll
    for (int i = 0; i < 16; i++) {
        float xi = xr[i];
#pragma unroll
        for (int o = 0; o < 16; o++) qs[o] = fmaf(xi, sWs[i * 16 + o], qs[o]);
    }
    float qv[24];
#pragma unroll
    for (int o = 0; o < 24; o++) qv[o] = 0.f;
#pragma unroll
    for (int i = 0; i < 8; i++) {
#pragma unroll
        for (int o = 0; o < 8; o++) {
            float w = sWv[i * 8 + o];
            qv[3 * o + 0] = fmaf(xr[16 + 3 * i + 0], w, qv[3 * o + 0]);
            qv[3 * o + 1] = fmaf(xr[16 + 3 * i + 1], w, qv[3 * o + 1]);
            qv[3 * o + 2] = fmaf(xr[16 + 3 * i + 2], w, qv[3 * o + 2]);
        }
    }
    float* qp = g_q + (size_t)n * DD;
#pragma unroll
    for (int c = 0; c < 16; c++) qp[c] = qs[c];
#pragma unroll
    for (int c = 0; c < 24; c++) qp[16 + c] = qv[c];
}

// ---------------- chunk load (128 rows x 32 floats) ----------------
__device__ __forceinline__ void load_chunk(const float* __restrict__ gsrc, const float* __restrict__ gb,
                                           float* sW2, float* sb2, int tid) {
    __syncthreads();
    const float4* sp = (const float4*)gsrc;
    float4* dp = (float4*)sW2;
#pragma unroll
    for (int q = 0; q < 8; q++) dp[tid + 128 * q] = sp[tid + 128 * q];
    if (tid < 128) sb2[tid] = gb[tid];
    __syncthreads();
}

// ---------------- edge branch; node features read from smem ----------------
// sXs layout: [16][256] (col = half*128+tid); sXv: [24][256]
template <int B>
__device__ __forceinline__ void run_branch(const u64 (&rhA)[16], const u64 (&rhB)[16],
                                           const float* __restrict__ sXs, const float* __restrict__ sXv,
                                           float shsA, float sA0, float sA1, float sA2,
                                           float shsB, float sB0, float sB1, float sB2,
                                           int tid, int eA, int eB, int srcA, int srcB,
                                           float* sW2, float* sb2) {
    float outsA[16], outsB[16];
#pragma unroll
    for (int o = 0; o < 16; o++) { outsA[o] = 0.f; outsB[o] = 0.f; }

    // chunks 0,1: w1 (16x16)
    load_chunk(g_W2T[B], g_b2[B], sW2, sb2, tid);
#pragma unroll 1
    for (int i = 0; i < 8; i++) {
        float aA = sXs[i * 256 + tid] * shsA;
        float aB = sXs[i * 256 + 128 + tid] * shsB;
#pragma unroll
        for (int o = 0; o < 16; o++) {
            float wA, wB;
            dot2(rhA, rhB, sW2 + (i * 16 + o) * 32, sb2[i * 16 + o], wA, wB);
            outsA[o] = fmaf(wA, aA, outsA[o]);
            outsB[o] = fmaf(wB, aB, outsB[o]);
        }
    }
    load_chunk(g_W2T[B] + 128 * 32, g_b2[B] + 128, sW2, sb2, tid);
#pragma unroll 1
    for (int i = 0; i < 8; i++) {
        float aA = sXs[(8 + i) * 256 + tid] * shsA;
        float aB = sXs[(8 + i) * 256 + 128 + tid] * shsB;
#pragma unroll
        for (int o = 0; o < 16; o++) {
            float wA, wB;
            dot2(rhA, rhB, sW2 + (i * 16 + o) * 32, sb2[i * 16 + o], wA, wB);
            outsA[o] = fmaf(wA, aA, outsA[o]);
            outsB[o] = fmaf(wB, aB, outsB[o]);
        }
    }
    // chunk 2: w2 (8x16)
    load_chunk(g_W2T[B] + 256 * 32, g_b2[B] + 256, sW2, sb2, tid);
#pragma unroll 1
    for (int i = 0; i < 8; i++) {
        float vA0 = sXv[(3 * i + 0) * 256 + tid], vA1 = sXv[(3 * i + 1) * 256 + tid], vA2 = sXv[(3 * i + 2) * 256 + tid];
        float vB0 = sXv[(3 * i + 0) * 256 + 128 + tid], vB1 = sXv[(3 * i + 1) * 256 + 128 + tid], vB2 = sXv[(3 * i + 2) * 256 + 128 + tid];
        float dA = C110 * (vA0 * sA0 + vA1 * sA1 + vA2 * sA2);
        float dB = C110 * (vB0 * sB0 + vB1 * sB1 + vB2 * sB2);
#pragma unroll
        for (int o = 0; o < 16; o++) {
            float wA, wB;
            dot2(rhA, rhB, sW2 + (i * 16 + o) * 32, sb2[i * 16 + o], wA, wB);
            outsA[o] = fmaf(wA, dA, outsA[o]);
            outsB[o] = fmaf(wB, dB, outsB[o]);
        }
    }
    // ---- retire outs ----
    float accA = 0.f, accB = 0.f;
    if (B == 0) {
        const float4* qa = (const float4*)(g_q + (size_t)srcA * DD);
        const float4* qb = (const float4*)(g_q + (size_t)srcB * DD);
#pragma unroll
        for (int q = 0; q < 4; q++) {
            float4 ta = qa[q], tb = qb[q];
            accA = fmaf(outsA[4 * q + 0], ta.x, accA); accA = fmaf(outsA[4 * q + 1], ta.y, accA);
            accA = fmaf(outsA[4 * q + 2], ta.z, accA); accA = fmaf(outsA[4 * q + 3], ta.w, accA);
            accB = fmaf(outsB[4 * q + 0], tb.x, accB); accB = fmaf(outsB[4 * q + 1], tb.y, accB);
            accB = fmaf(outsB[4 * q + 2], tb.z, accB); accB = fmaf(outsB[4 * q + 3], tb.w, accB);
        }
    } else {
        float4* va = (float4*)(g_vedge + (size_t)eA * DD);
        float4* vb = (float4*)(g_vedge + (size_t)eB * DD);
#pragma unroll
        for (int q = 0; q < 4; q++) {
            va[q] = make_float4(outsA[4 * q + 0], outsA[4 * q + 1], outsA[4 * q + 2], outsA[4 * q + 3]);
            vb[q] = make_float4(outsB[4 * q + 0], outsB[4 * q + 1], outsB[4 * q + 2], outsB[4 * q + 3]);
        }
    }

    float outvA[24], outvB[24];
#pragma unroll
    for (int o = 0; o < 24; o++) { outvA[o] = 0.f; outvB[o] = 0.f; }

    // chunk 3: w3 (16x8)
    load_chunk(g_W2T[B] + 384 * 32, g_b2[B] + 384, sW2, sb2, tid);
#pragma unroll 1
    for (int i = 0; i < 16; i++) {
        float xA = sXs[i * 256 + tid], xB = sXs[i * 256 + 128 + tid];
        float tA0 = xA * sA0, tA1 = xA * sA1, tA2 = xA * sA2;
        float tB0 = xB * sB0, tB1 = xB * sB1, tB2 = xB * sB2;
#pragma unroll
        for (int o = 0; o < 8; o++) {
            float wA, wB;
            dot2(rhA, rhB, sW2 + (i * 8 + o) * 32, sb2[i * 8 + o], wA, wB);
            outvA[3 * o + 0] = fmaf(wA, tA0, outvA[3 * o + 0]);
            outvA[3 * o + 1] = fmaf(wA, tA1, outvA[3 * o + 1]);
            outvA[3 * o + 2] = fmaf(wA, tA2, outvA[3 * o + 2]);
            outvB[3 * o + 0] = fmaf(wB, tB0, outvB[3 * o + 0]);
            outvB[3 * o + 1] = fmaf(wB, tB1, outvB[3 * o + 1]);
            outvB[3 * o + 2] = fmaf(wB, tB2, outvB[3 * o + 2]);
        }
    }
    // chunk 4: w4 + w5
    load_chunk(g_W2T[B] + 512 * 32, g_b2[B] + 512, sW2, sb2, tid);
#pragma unroll 1
    for (int i = 0; i < 8; i++) {
        float tA0 = sXv[(3 * i + 0) * 256 + tid] * shsA;
        float tA1 = sXv[(3 * i + 1) * 256 + tid] * shsA;
        float tA2 = sXv[(3 * i + 2) * 256 + tid] * shsA;
        float tB0 = sXv[(3 * i + 0) * 256 + 128 + tid] * shsB;
        float tB1 = sXv[(3 * i + 1) * 256 + 128 + tid] * shsB;
        float tB2 = sXv[(3 * i + 2) * 256 + 128 + tid] * shsB;
#pragma unroll
        for (int o = 0; o < 8; o++) {
            float wA, wB;
            dot2(rhA, rhB, sW2 + (i * 8 + o) * 32, sb2[i * 8 + o], wA, wB);
            outvA[3 * o + 0] = fmaf(wA, tA0, outvA[3 * o + 0]);
            outvA[3 * o + 1] = fmaf(wA, tA1, outvA[3 * o + 1]);
            outvA[3 * o + 2] = fmaf(wA, tA2, outvA[3 * o + 2]);
            outvB[3 * o + 0] = fmaf(wB, tB0, outvB[3 * o + 0]);
            outvB[3 * o + 1] = fmaf(wB, tB1, outvB[3 * o + 1]);
            outvB[3 * o + 2] = fmaf(wB, tB2, outvB[3 * o + 2]);
        }
    }
#pragma unroll 1
    for (int i = 0; i < 8; i++) {
        float aA0 = sXv[(3 * i + 0) * 256 + tid], aA1 = sXv[(3 * i + 1) * 256 + tid], aA2 = sXv[(3 * i + 2) * 256 + tid];
        float cA0 = C111 * (aA1 * sA2 - aA2 * sA1);
        float cA1 = C111 * (aA2 * sA0 - aA0 * sA2);
        float cA2 = C111 * (aA0 * sA1 - aA1 * sA0);
        float aB0 = sXv[(3 * i + 0) * 256 + 128 + tid], aB1 = sXv[(3 * i + 1) * 256 + 128 + tid], aB2 = sXv[(3 * i + 2) * 256 + 128 + tid];
        float cB0 = C111 * (aB1 * sB2 - aB2 * sB1);
        float cB1 = C111 * (aB2 * sB0 - aB0 * sB2);
        float cB2 = C111 * (aB0 * sB1 - aB1 * sB0);
#pragma unroll
        for (int o = 0; o < 8; o++) {
            float wA, wB;
            dot2(rhA, rhB, sW2 + (64 + i * 8 + o) * 32, sb2[64 + i * 8 + o], wA, wB);
            outvA[3 * o + 0] = fmaf(wA, cA0, outvA[3 * o + 0]);
            outvA[3 * o + 1] = fmaf(wA, cA1, outvA[3 * o + 1]);
            outvA[3 * o + 2] = fmaf(wA, cA2, outvA[3 * o + 2]);
            outvB[3 * o + 0] = fmaf(wB, cB0, outvB[3 * o + 0]);
            outvB[3 * o + 1] = fmaf(wB, cB1, outvB[3 * o + 1]);
            outvB[3 * o + 2] = fmaf(wB, cB2, outvB[3 * o + 2]);
        }
    }
    // ---- retire outv ----
    if (B == 0) {
        const float* qa = g_q + (size_t)srcA * DD + 16;
        const float* qb = g_q + (size_t)srcB * DD + 16;
#pragma unroll
        for (int c = 0; c < 24; c++) {
            accA = fmaf(outvA[c], qa[c], accA);
            accB = fmaf(outvB[c], qb[c], accB);
        }
        g_attn[eA] = accA;
        g_attn[eB] = accB;
    } else {
        float4* va = (float4*)(g_vedge + (size_t)eA * DD + 16);
        float4* vb = (float4*)(g_vedge + (size_t)eB * DD + 16);
#pragma unroll
        for (int q = 0; q < 6; q++) {
            va[q] = make_float4(outvA[4 * q + 0], outvA[4 * q + 1], outvA[4 * q + 2], outvA[4 * q + 3]);
            vb[q] = make_float4(outvB[4 * q + 0], outvB[4 * q + 1], outvB[4 * q + 2], outvB[4 * q + 3]);
        }
    }
}

// ---------------- hidden layer for one branch (both edges) ----------------
__device__ __forceinline__ void hidden_branch(const float* __restrict__ efeat, int eA, int eB,
                                              const float* __restrict__ sW1b, const float* __restrict__ sB1b,
                                              u64 (&rhA)[16], u64 (&rhB)[16]) {
    u64 efA[16], efB[16];
    const ulonglong2* pa = (const ulonglong2*)(efeat + (size_t)eA * HE);
    const ulonglong2* pb = (const ulonglong2*)(efeat + (size_t)eB * HE);
#pragma unroll
    for (int q = 0; q < 8; q++) {
        ulonglong2 ta = pa[q], tb = pb[q];
        efA[2 * q] = ta.x; efA[2 * q + 1] = ta.y;
        efB[2 * q] = tb.x; efB[2 * q + 1] = tb.y;
    }
#pragma unroll 1
    for (int t = 0; t < 32; t += 2) {
        float kA0, kB0, kA1, kB1;
        dot2(efA, efB, sW1b + t * 32, sB1b[t], kA0, kB0);
        dot2(efA, efB, sW1b + (t + 1) * 32, sB1b[t + 1], kA1, kB1);
        rhA[t >> 1] = packf2(fmaxf(kA0, 0.f), fmaxf(kA1, 0.f));
        rhB[t >> 1] = packf2(fmaxf(kB0, 0.f), fmaxf(kB1, 0.f));
    }
}

// ---------------- main edge kernel: 2 edges per thread, 3 CTAs/SM ----------------
// dynamic smem layout (floats): sW1[2048] | sW2[4096] | sXs[16*256] | sXv[24*256] | sb1[64] | sb2[128]
#define SMEM_EDGE ((2048 + 4096 + 16 * 256 + 24 * 256 + 64 + 128) * 4)

__global__ void __launch_bounds__(128, 3) edge_kernel(const float* __restrict__ atom,
                                                      const float* __restrict__ efeat,
                                                      const float* __restrict__ esh,
                                                      const int* __restrict__ eidx) {
    extern __shared__ float smem[];
    float* sW1 = smem;            // 2048
    float* sW2 = sW1 + 2048;      // 4096
    float* sXs = sW2 + 4096;      // 4096
    float* sXv = sXs + 4096;      // 6144
    float* sb1 = sXv + 6144;      // 64
    float* sb2 = sb1 + 64;        // 128

    const int tid = threadIdx.x;
    const int eA = blockIdx.x * 256 + tid;
    const int eB = eA + 128;

    for (int i = tid; i < 2048; i += 128) sW1[i] = ((const float*)g_W1T)[i];
    if (tid < 64) sb1[tid] = ((const float*)g_b1)[tid];

    const int dstA = eidx[eA], srcA = eidx[NE + eA];
    const int dstB = eidx[eB], srcB = eidx[NE + eB];
    atomicAdd(&g_count[srcA], 1);
    atomicAdd(&g_count[srcB], 1);

    // stage node features for both edges into smem (feature-major, conflict-free columns)
    {
        const float4* pa = (const float4*)(atom + (size_t)dstA * DD);
        const float4* pb = (const float4*)(atom + (size_t)dstB * DD);
#pragma unroll
        for (int q = 0; q < 4; q++) {
            float4 t = pa[q];
            sXs[(4 * q + 0) * 256 + tid] = t.x; sXs[(4 * q + 1) * 256 + tid] = t.y;
            sXs[(4 * q + 2) * 256 + tid] = t.z; sXs[(4 * q + 3) * 256 + tid] = t.w;
            t = pb[q];
            sXs[(4 * q + 0) * 256 + 128 + tid] = t.x; sXs[(4 * q + 1) * 256 + 128 + tid] = t.y;
            sXs[(4 * q + 2) * 256 + 128 + tid] = t.z; sXs[(4 * q + 3) * 256 + 128 + tid] = t.w;
        }
#pragma unroll
        for (int q = 0; q < 6; q++) {
            float4 t = pa[4 + q];
            sXv[(4 * q + 0) * 256 + tid] = t.x; sXv[(4 * q + 1) * 256 + tid] = t.y;
            sXv[(4 * q + 2) * 256 + tid] = t.z; sXv[(4 * q + 3) * 256 + tid] = t.w;
            t = pb[4 + q];
            sXv[(4 * q + 0) * 256 + 128 + tid] = t.x; sXv[(4 * q + 1) * 256 + 128 + tid] = t.y;
            sXv[(4 * q + 2) * 256 + 128 + tid] = t.z; sXv[(4 * q + 3) * 256 + 128 + tid] = t.w;
        }
    }
    float4 shA = *(const float4*)(esh + (size_t)eA * 4);
    float4 shB = *(const float4*)(esh + (size_t)eB * 4);
    __syncthreads();

    u64 rhA[16], rhB[16];

    // ---- k branch ----
    hidden_branch(efeat, eA, eB, sW1, sb1, rhA, rhB);
    run_branch<0>(rhA, rhB, sXs, sXv,
                  shA.x, shA.y, shA.z, shA.w, shB.x, shB.y, shB.z, shB.w,
                  tid, eA, eB, srcA, srcB, sW2, sb2);

    // ---- v branch (recompute hidden; efeat is L2-resident) ----
    hidden_branch(efeat, eA, eB, sW1 + 1024, sb1 + 32, rhA, rhB);
    run_branch<1>(rhA, rhB, sXs, sXv,
                  shA.x, shA.y, shA.z, shA.w, shB.x, shB.y, shB.z, shB.w,
                  tid, eA, eB, srcA, srcB, sW2, sb2);
}

// ---------------- CSR build: scan ----------------
__global__ void scan_kernel() {
    __shared__ int part[256];
    int tid = threadIdx.x;
    const int CH = (NN + 255) / 256;
    int beg = tid * CH;
    int end = beg + CH < NN ? beg + CH : NN;
    int s = 0;
    for (int i = beg; i < end; i++) s += g_count[i];
    part[tid] = s;
    __syncthreads();
    if (tid == 0) {
        int acc = 0;
        for (int i = 0; i < 256; i++) { int t = part[i]; part[i] = acc; acc += t; }
    }
    __syncthreads();
    int acc = part[tid];
    for (int i = beg; i < end; i++) {
        g_off[i] = acc;
        g_cursor[i] = acc;
        acc += g_count[i];
    }
    if (tid == 255) g_off[NN] = acc;
}

// ---------------- CSR build: scatter ----------------
__global__ void scatter_kernel(const int* __restrict__ eidx) {
    int e = blockIdx.x * 256 + threadIdx.x;
    int src = eidx[NE + e];
    int pos = atomicAdd(&g_cursor[src], 1);
    g_elist[pos] = e;
}

// ---------------- per-node softmax + aggregation + residual + stats ----------------
__global__ void gather_kernel(const float* __restrict__ atom) {
    __shared__ float sacc[48];
    int tid = threadIdx.x;
    if (tid < 48) sacc[tid] = 0.f;
    __syncthreads();
    int lane = tid & 31;
    int n = blockIdx.x * 4 + (tid >> 5);
    float x0 = 0.f, x1 = 0.f;
    {
        int beg = g_off[n], end = g_off[n + 1];
        float m = -INFINITY;
        for (int j = beg + lane; j < end; j += 32) m = fmaxf(m, g_attn[g_elist[j]]);
#pragma unroll
        for (int o = 16; o; o >>= 1) m = fmaxf(m, __shfl_xor_sync(~0u, m, o));
        if (!isfinite(m)) m = 0.f;
        float ds = 0.f;
        for (int j = beg + lane; j < end; j += 32) ds += expf(g_attn[g_elist[j]] - m);
#pragma unroll
        for (int o = 16; o; o >>= 1) ds += __shfl_xor_sync(~0u, ds, o);
        float a0 = 0.f, a1 = 0.f;
        for (int j = beg; j < end; j++) {
            int e = g_elist[j];
            float ev = expf(g_attn[e] - m);
            const float* vp = g_vedge + (size_t)e * DD;
            a0 = fmaf(ev, vp[lane], a0);
            if (lane < 8) a1 = fmaf(ev, vp[32 + lane], a1);
        }
        float inv = (ds != 0.f) ? 1.f / ds : 0.f;
        x0 = atom[(size_t)n * DD + lane] + a0 * inv;
        g_num[(size_t)n * DD + lane] = x0;
        if (lane < 8) {
            x1 = atom[(size_t)n * DD + 32 + lane] + a1 * inv;
            g_num[(size_t)n * DD + 32 + lane] = x1;
        }
    }
    if (lane < 16) {
        atomicAdd(&sacc[lane], x0);
        atomicAdd(&sacc[16 + lane], x0 * x0);
    } else {
        atomicAdd(&sacc[32 + (lane - 16) / 3], x0 * x0);
    }
    if (lane < 8) atomicAdd(&sacc[32 + (lane + 16) / 3], x1 * x1);
    __syncthreads();
    if (tid < 48) atomicAdd(&g_stats[tid], sacc[tid]);
}

// ---------------- finalize: batchnorm + write ----------------
__global__ void finalB_kernel(float* __restrict__ out,
                              const float* __restrict__ ws, const float* __restrict__ bs,
                              const float* __restrict__ wv) {
    int n = blockIdx.x * 256 + threadIdx.x;
    if (n >= NN) return;
    const float invN = 1.f / (float)NN;
#pragma unroll
    for (int c = 0; c < 16; c++) {
        float mu = g_stats[c] * invN;
        float var = g_stats[16 + c] * invN - mu * mu;
        float x = g_num[(size_t)n * DD + c];
        out[(size_t)n * DD + c] = (x - mu) / sqrtf(var + EPSV) * ws[c] + bs[c];
    }
#pragma unroll
    for (int i = 0; i < 8; i++) {
        float norm = g_stats[32 + i] * (invN * (1.f / 3.f));
        float sc = wv[i] / sqrtf(norm + EPSV);
#pragma unroll
        for (int d = 0; d < 3; d++) {
            float x = g_num[(size_t)n * DD + 16 + 3 * i + d];
            out[(size_t)n * DD + 16 + 3 * i + d] = x * sc;
        }
    }
}

// ---------------- launch ----------------
extern "C" void kernel_launch(void* const* d_in, const int* in_sizes, int n_in,
                              void* d_out, int out_size) {
    const float* atom  = (const float*)d_in[0];
    const float* efeat = (const float*)d_in[1];
    const float* esh   = (const float*)d_in[2];
    const float* Wqs   = (const float*)d_in[3];
    const float* Wqv   = (const float*)d_in[4];
    const float* kw1   = (const float*)d_in[5];
    const float* kb1   = (const float*)d_in[6];
    const float* kw2   = (const float*)d_in[7];
    const float* kb2   = (const float*)d_in[8];
    const float* vw1   = (const float*)d_in[9];
    const float* vb1   = (const float*)d_in[10];
    const float* vw2   = (const float*)d_in[11];
    const float* vb2   = (const float*)d_in[12];
    const float* bnws  = (const float*)d_in[13];
    const float* bnbs  = (const float*)d_in[14];
    const float* bnwv  = (const float*)d_in[15];
    const int*   eidx  = (const int*)d_in[16];
    float* out = (float*)d_out;

    cudaFuncSetAttribute(edge_kernel, cudaFuncAttributeMaxDynamicSharedMemorySize, SMEM_EDGE);

    init_kernel<<<(NN + 255) / 256, 256>>>();
    prep_kernel<<<(2 * 22176 + 255) / 256, 256>>>(kw1, kb1, kw2, kb2, vw1, vb1, vw2, vb2);
    qnode_kernel<<<(NN + 255) / 256, 256>>>(atom, Wqs, Wqv);
    edge_kernel<<<NE / 256, 128, SMEM_EDGE>>>(atom, efeat, esh, eidx);
    scan_kernel<<<1, 256>>>();
    scatter_kernel<<<NE / 256, 256>>>(eidx);
    gather_kernel<<<NN / 4, 128>>>(atom);
    finalB_kernel<<<(NN + 255) / 256, 256>>>(out, bnws, bnbs, bnwv);
    cudaMemcpyAsync(out + NN * DD, efeat, (size_t)NE * HE * sizeof(float),
                    cudaMemcpyDeviceToDevice);
}

// round 6
// speedup vs baseline: 1.0916x; 1.0212x over previous
#include <cuda_runtime.h>
#include <cuda_bf16.h>
#include <math.h>

#define NS 16
#define NV 8
#define HE 32
#define DD 40
#define WN 640
#define NE 160000
#define NN 10000
#define C110 0.57735026918962576451f
#define C111 0.70710678118654752440f
#define EPSV 1e-5f

typedef unsigned long long u64;

// ---------------- scratch ----------------
__device__ __align__(16) float g_q[NN * DD];
__device__ __align__(16) float g_W1T[2][32 * 32];
__device__ __align__(16) float g_W2T[2][WN * 32];
__device__ __align__(16) float g_b1[2][32];
__device__ __align__(16) float g_b2[2][WN];
__device__ __align__(16) float g_attn[NE];
__device__ __align__(16) float g_vedge[(size_t)NE * DD];
__device__ __align__(16) float g_num[NN * DD];
__device__ float g_stats[48];
__device__ int g_count[NN];
__device__ int g_off[NN + 1];
__device__ int g_cursor[NN];
__device__ int g_elist[NE];

// ---------------- packed helpers ----------------
__device__ __forceinline__ u64 packf2(float lo, float hi) {
    u64 p; asm("mov.b64 %0, {%1, %2};" : "=l"(p) : "f"(lo), "f"(hi)); return p;
}
__device__ __forceinline__ u64 fma2(u64 a, u64 b, u64 c) {
    u64 r; asm("fma.rn.f32x2 %0, %1, %2, %3;" : "=l"(r) : "l"(a), "l"(b), "l"(c)); return r;
}
__device__ __forceinline__ u64 add2(u64 a, u64 b) {
    u64 r; asm("add.rn.f32x2 %0, %1, %2;" : "=l"(r) : "l"(a), "l"(b)); return r;
}
__device__ __forceinline__ void unpack2(u64 a, float& lo, float& hi) {
    asm("mov.b64 {%0, %1}, %2;" : "=f"(lo), "=f"(hi) : "l"(a));
}

// dual dot: one weight-row load feeds two packed dot products
__device__ __forceinline__ void dot2(const u64 (&ra)[16], const u64 (&rb)[16],
                                     const float* __restrict__ row, float bias,
                                     float& da, float& db) {
    const ulonglong2* wp = (const ulonglong2*)row;
    u64 a0 = 0ULL, a1 = 0ULL, a2 = 0ULL, a3 = 0ULL;
    u64 b0 = 0ULL, b1 = 0ULL, b2 = 0ULL, b3 = 0ULL;
#pragma unroll
    for (int q = 0; q < 4; q++) {
        ulonglong2 w0 = wp[2 * q];
        ulonglong2 w1 = wp[2 * q + 1];
        a0 = fma2(ra[4 * q + 0], w0.x, a0);
        b0 = fma2(rb[4 * q + 0], w0.x, b0);
        a1 = fma2(ra[4 * q + 1], w0.y, a1);
        b1 = fma2(rb[4 * q + 1], w0.y, b1);
        a2 = fma2(ra[4 * q + 2], w1.x, a2);
        b2 = fma2(rb[4 * q + 2], w1.x, b2);
        a3 = fma2(ra[4 * q + 3], w1.y, a3);
        b3 = fma2(rb[4 * q + 3], w1.y, b3);
    }
    a0 = add2(a0, a1); a2 = add2(a2, a3); a0 = add2(a0, a2);
    b0 = add2(b0, b1); b2 = add2(b2, b3); b0 = add2(b0, b2);
    float alo, ahi, blo, bhi;
    unpack2(a0, alo, ahi);
    unpack2(b0, blo, bhi);
    da = (alo + ahi) + bias;
    db = (blo + bhi) + bias;
}

// ---------------- init ----------------
__global__ void init_kernel() {
    int i = blockIdx.x * blockDim.x + threadIdx.x;
    if (i < NN) g_count[i] = 0;
    if (i < 48) g_stats[i] = 0.f;
}

// ---------------- weight transpose / copy ----------------
__global__ void prep_kernel(const float* __restrict__ kw1, const float* __restrict__ kb1,
                            const float* __restrict__ kw2, const float* __restrict__ kb2,
                            const float* __restrict__ vw1, const float* __restrict__ vb1,
                            const float* __restrict__ vw2, const float* __restrict__ vb2) {
    const int PER = WN * 32 + 1024 + 32 + WN;
    int id = blockIdx.x * blockDim.x + threadIdx.x;
    if (id >= 2 * PER) return;
    int b = id / PER, r = id % PER;
    const float* w1 = b ? vw1 : kw1;
    const float* w2 = b ? vw2 : kw2;
    const float* b1 = b ? vb1 : kb1;
    const float* b2 = b ? vb2 : kb2;
    if (r < WN * 32) {
        int j = r >> 5, t = r & 31;
        g_W2T[b][r] = w2[t * WN + j];
    } else if (r < WN * 32 + 1024) {
        int q = r - WN * 32;
        int t = q >> 5, c = q & 31;
        g_W1T[b][q] = w1[c * 32 + t];
    } else if (r < WN * 32 + 1024 + 32) {
        g_b1[b][r - (WN * 32 + 1024)] = b1[r - (WN * 32 + 1024)];
    } else {
        g_b2[b][r - (WN * 32 + 1024 + 32)] = b2[r - (WN * 32 + 1024 + 32)];
    }
}

// ---------------- q projection ----------------
__global__ void qnode_kernel(const float* __restrict__ atom,
                             const float* __restrict__ Wqs, const float* __restrict__ Wqv) {
    __shared__ float sWs[256];
    __shared__ float sWv[64];
    int tid = threadIdx.x;
    if (tid < 256) sWs[tid] = Wqs[tid];
    if (tid < 64) sWv[tid] = Wqv[tid];
    __syncthreads();
    int n = blockIdx.x * 256 + tid;
    if (n >= NN) return;
    float xr[DD];
    const float4* p = (const float4*)(atom + (size_t)n * DD);
#pragma unroll
    for (int q = 0; q < 10; q++) {
        float4 t = p[q];
        xr[4 * q + 0] = t.x; xr[4 * q + 1] = t.y; xr[4 * q + 2] = t.z; xr[4 * q + 3] = t.w;
    }
    float qs[16];
#pragma unroll
    for (int o = 0; o < 16; o++) qs[o] = 0.f;
#pragma unroll
    for (int i = 0; i < 16; i++) {
        float xi = xr[i];
#pragma unroll
        for (int o = 0; o < 16; o++) qs[o] = fmaf(xi, sWs[i * 16 + o], qs[o]);
    }
    float qv[24];
#pragma unroll
    for (int o = 0; o < 24; o++) qv[o] = 0.f;
#pragma unroll
    for (int i = 0; i < 8; i++) {
#pragma unroll
        for (int o = 0; o < 8; o++) {
            float w = sWv[i * 8 + o];
            qv[3 * o + 0] = fmaf(xr[16 + 3 * i + 0], w, qv[3 * o + 0]);
            qv[3 * o + 1] = fmaf(xr[16 + 3 * i + 1], w, qv[3 * o + 1]);
            qv[3 * o + 2] = fmaf(xr[16 + 3 * i + 2], w, qv[3 * o + 2]);
        }
    }
    float* qp = g_q + (size_t)n * DD;
#pragma unroll
    for (int c = 0; c < 16; c++) qp[c] = qs[c];
#pragma unroll
    for (int c = 0; c < 24; c++) qp[16 + c] = qv[c];
}

// ---------------- chunk load (128 rows x 32 floats) ----------------
__device__ __forceinline__ void load_chunk(const float* __restrict__ gsrc, const float* __restrict__ gb,
                                           float* sW2, float* sb2, int tid) {
    __syncthreads();
    const float4* sp = (const float4*)gsrc;
    float4* dp = (float4*)sW2;
#pragma unroll
    for (int q = 0; q < 8; q++) dp[tid + 128 * q] = sp[tid + 128 * q];
    if (tid < 128) sb2[tid] = gb[tid];
    __syncthreads();
}

// ---------------- edge branch; node features read from smem ----------------
// sXs layout: [16][256] (col = half*128+tid); sXv: [24][256]
template <int B>
__device__ __forceinline__ void run_branch(const u64 (&rhA)[16], const u64 (&rhB)[16],
                                           const float* __restrict__ sXs, const float* __restrict__ sXv,
                                           float shsA, float sA0, float sA1, float sA2,
                                           float shsB, float sB0, float sB1, float sB2,
                                           int tid, int eA, int eB, int srcA, int srcB,
                                           float* sW2, float* sb2) {
    float outsA[16], outsB[16];
#pragma unroll
    for (int o = 0; o < 16; o++) { outsA[o] = 0.f; outsB[o] = 0.f; }

    // chunks 0,1: w1 (16x16)
    load_chunk(g_W2T[B], g_b2[B], sW2, sb2, tid);
#pragma unroll 1
    for (int i = 0; i < 8; i++) {
        float aA = sXs[i * 256 + tid] * shsA;
        float aB = sXs[i * 256 + 128 + tid] * shsB;
#pragma unroll
        for (int o = 0; o < 16; o++) {
            float wA, wB;
            dot2(rhA, rhB, sW2 + (i * 16 + o) * 32, sb2[i * 16 + o], wA, wB);
            outsA[o] = fmaf(wA, aA, outsA[o]);
            outsB[o] = fmaf(wB, aB, outsB[o]);
        }
    }
    load_chunk(g_W2T[B] + 128 * 32, g_b2[B] + 128, sW2, sb2, tid);
#pragma unroll 1
    for (int i = 0; i < 8; i++) {
        float aA = sXs[(8 + i) * 256 + tid] * shsA;
        float aB = sXs[(8 + i) * 256 + 128 + tid] * shsB;
#pragma unroll
        for (int o = 0; o < 16; o++) {
            float wA, wB;
            dot2(rhA, rhB, sW2 + (i * 16 + o) * 32, sb2[i * 16 + o], wA, wB);
            outsA[o] = fmaf(wA, aA, outsA[o]);
            outsB[o] = fmaf(wB, aB, outsB[o]);
        }
    }
    // chunk 2: w2 (8x16)
    load_chunk(g_W2T[B] + 256 * 32, g_b2[B] + 256, sW2, sb2, tid);
#pragma unroll 1
    for (int i = 0; i < 8; i++) {
        float vA0 = sXv[(3 * i + 0) * 256 + tid], vA1 = sXv[(3 * i + 1) * 256 + tid], vA2 = sXv[(3 * i + 2) * 256 + tid];
        float vB0 = sXv[(3 * i + 0) * 256 + 128 + tid], vB1 = sXv[(3 * i + 1) * 256 + 128 + tid], vB2 = sXv[(3 * i + 2) * 256 + 128 + tid];
        float dA = C110 * (vA0 * sA0 + vA1 * sA1 + vA2 * sA2);
        float dB = C110 * (vB0 * sB0 + vB1 * sB1 + vB2 * sB2);
#pragma unroll
        for (int o = 0; o < 16; o++) {
            float wA, wB;
            dot2(rhA, rhB, sW2 + (i * 16 + o) * 32, sb2[i * 16 + o], wA, wB);
            outsA[o] = fmaf(wA, dA, outsA[o]);
            outsB[o] = fmaf(wB, dB, outsB[o]);
        }
    }
    // ---- retire outs ----
    float accA = 0.f, accB = 0.f;
    if (B == 0) {
        const float4* qa = (const float4*)(g_q + (size_t)srcA * DD);
        const float4* qb = (const float4*)(g_q + (size_t)srcB * DD);
#pragma unroll
        for (int q = 0; q < 4; q++) {
            float4 ta = qa[q], tb = qb[q];
            accA = fmaf(outsA[4 * q + 0], ta.x, accA); accA = fmaf(outsA[4 * q + 1], ta.y, accA);
            accA = fmaf(outsA[4 * q + 2], ta.z, accA); accA = fmaf(outsA[4 * q + 3], ta.w, accA);
            accB = fmaf(outsB[4 * q + 0], tb.x, accB); accB = fmaf(outsB[4 * q + 1], tb.y, accB);
            accB = fmaf(outsB[4 * q + 2], tb.z, accB); accB = fmaf(outsB[4 * q + 3], tb.w, accB);
        }
    } else {
        float4* va = (float4*)(g_vedge + (size_t)eA * DD);
        float4* vb = (float4*)(g_vedge + (size_t)eB * DD);
#pragma unroll
        for (int q = 0; q < 4; q++) {
            va[q] = make_float4(outsA[4 * q + 0], outsA[4 * q + 1], outsA[4 * q + 2], outsA[4 * q + 3]);
            vb[q] = make_float4(outsB[4 * q + 0], outsB[4 * q + 1], outsB[4 * q + 2], outsB[4 * q + 3]);
        }
    }

    float outvA[24], outvB[24];
#pragma unroll
    for (int o = 0; o < 24; o++) { outvA[o] = 0.f; outvB[o] = 0.f; }

    // chunk 3: w3 (16x8)
    load_chunk(g_W2T[B] + 384 * 32, g_b2[B] + 384, sW2, sb2, tid);
#pragma unroll 1
    for (int i = 0; i < 16; i++) {
        float xA = sXs[i * 256 + tid], xB = sXs[i * 256 + 128 + tid];
        float tA0 = xA * sA0, tA1 = xA * sA1, tA2 = xA * sA2;
        float tB0 = xB * sB0, tB1 = xB * sB1, tB2 = xB * sB2;
#pragma unroll
        for (int o = 0; o < 8; o++) {
            float wA, wB;
            dot2(rhA, rhB, sW2 + (i * 8 + o) * 32, sb2[i * 8 + o], wA, wB);
            outvA[3 * o + 0] = fmaf(wA, tA0, outvA[3 * o + 0]);
            outvA[3 * o + 1] = fmaf(wA, tA1, outvA[3 * o + 1]);
            outvA[3 * o + 2] = fmaf(wA, tA2, outvA[3 * o + 2]);
            outvB[3 * o + 0] = fmaf(wB, tB0, outvB[3 * o + 0]);
            outvB[3 * o + 1] = fmaf(wB, tB1, outvB[3 * o + 1]);
            outvB[3 * o + 2] = fmaf(wB, tB2, outvB[3 * o + 2]);
        }
    }
    // chunk 4: w4 + w5
    load_chunk(g_W2T[B] + 512 * 32, g_b2[B] + 512, sW2, sb2, tid);
#pragma unroll 1
    for (int i = 0; i < 8; i++) {
        float tA0 = sXv[(3 * i + 0) * 256 + tid] * shsA;
        float tA1 = sXv[(3 * i + 1) * 256 + tid] * shsA;
        float tA2 = sXv[(3 * i + 2) * 256 + tid] * shsA;
        float tB0 = sXv[(3 * i + 0) * 256 + 128 + tid] * shsB;
        float tB1 = sXv[(3 * i + 1) * 256 + 128 + tid] * shsB;
        float tB2 = sXv[(3 * i + 2) * 256 + 128 + tid] * shsB;
#pragma unroll
        for (int o = 0; o < 8; o++) {
            float wA, wB;
            dot2(rhA, rhB, sW2 + (i * 8 + o) * 32, sb2[i * 8 + o], wA, wB);
            outvA[3 * o + 0] = fmaf(wA, tA0, outvA[3 * o + 0]);
            outvA[3 * o + 1] = fmaf(wA, tA1, outvA[3 * o + 1]);
            outvA[3 * o + 2] = fmaf(wA, tA2, outvA[3 * o + 2]);
            outvB[3 * o + 0] = fmaf(wB, tB0, outvB[3 * o + 0]);
            outvB[3 * o + 1] = fmaf(wB, tB1, outvB[3 * o + 1]);
            outvB[3 * o + 2] = fmaf(wB, tB2, outvB[3 * o + 2]);
        }
    }
#pragma unroll 1
    for (int i = 0; i < 8; i++) {
        float aA0 = sXv[(3 * i + 0) * 256 + tid], aA1 = sXv[(3 * i + 1) * 256 + tid], aA2 = sXv[(3 * i + 2) * 256 + tid];
        float cA0 = C111 * (aA1 * sA2 - aA2 * sA1);
        float cA1 = C111 * (aA2 * sA0 - aA0 * sA2);
        float cA2 = C111 * (aA0 * sA1 - aA1 * sA0);
        float aB0 = sXv[(3 * i + 0) * 256 + 128 + tid], aB1 = sXv[(3 * i + 1) * 256 + 128 + tid], aB2 = sXv[(3 * i + 2) * 256 + 128 + tid];
        float cB0 = C111 * (aB1 * sB2 - aB2 * sB1);
        float cB1 = C111 * (aB2 * sB0 - aB0 * sB2);
        float cB2 = C111 * (aB0 * sB1 - aB1 * sB0);
#pragma unroll
        for (int o = 0; o < 8; o++) {
            float wA, wB;
            dot2(rhA, rhB, sW2 + (64 + i * 8 + o) * 32, sb2[64 + i * 8 + o], wA, wB);
            outvA[3 * o + 0] = fmaf(wA, cA0, outvA[3 * o + 0]);
            outvA[3 * o + 1] = fmaf(wA, cA1, outvA[3 * o + 1]);
            outvA[3 * o + 2] = fmaf(wA, cA2, outvA[3 * o + 2]);
            outvB[3 * o + 0] = fmaf(wB, cB0, outvB[3 * o + 0]);
            outvB[3 * o + 1] = fmaf(wB, cB1, outvB[3 * o + 1]);
            outvB[3 * o + 2] = fmaf(wB, cB2, outvB[3 * o + 2]);
        }
    }
    // ---- retire outv ----
    if (B == 0) {
        const float* qa = g_q + (size_t)srcA * DD + 16;
        const float* qb = g_q + (size_t)srcB * DD + 16;
#pragma unroll
        for (int c = 0; c < 24; c++) {
            accA = fmaf(outvA[c], qa[c], accA);
            accB = fmaf(outvB[c], qb[c], accB);
        }
        g_attn[eA] = accA;
        g_attn[eB] = accB;
    } else {
        float4* va = (float4*)(g_vedge + (size_t)eA * DD + 16);
        float4* vb = (float4*)(g_vedge + (size_t)eB * DD + 16);
#pragma unroll
        for (int q = 0; q < 6; q++) {
            va[q] = make_float4(outvA[4 * q + 0], outvA[4 * q + 1], outvA[4 * q + 2], outvA[4 * q + 3]);
            vb[q] = make_float4(outvB[4 * q + 0], outvB[4 * q + 1], outvB[4 * q + 2], outvB[4 * q + 3]);
        }
    }
}

// ---------------- hidden layer for one branch (both edges) ----------------
__device__ __forceinline__ void hidden_branch(const float* __restrict__ efeat, int eA, int eB,
                                              const float* __restrict__ sW1b, const float* __restrict__ sB1b,
                                              u64 (&rhA)[16], u64 (&rhB)[16]) {
    u64 efA[16], efB[16];
    const ulonglong2* pa = (const ulonglong2*)(efeat + (size_t)eA * HE);
    const ulonglong2* pb = (const ulonglong2*)(efeat + (size_t)eB * HE);
#pragma unroll
    for (int q = 0; q < 8; q++) {
        ulonglong2 ta = pa[q], tb = pb[q];
        efA[2 * q] = ta.x; efA[2 * q + 1] = ta.y;
        efB[2 * q] = tb.x; efB[2 * q + 1] = tb.y;
    }
#pragma unroll 1
    for (int t = 0; t < 32; t += 2) {
        float kA0, kB0, kA1, kB1;
        dot2(efA, efB, sW1b + t * 32, sB1b[t], kA0, kB0);
        dot2(efA, efB, sW1b + (t + 1) * 32, sB1b[t + 1], kA1, kB1);
        rhA[t >> 1] = packf2(fmaxf(kA0, 0.f), fmaxf(kA1, 0.f));
        rhB[t >> 1] = packf2(fmaxf(kB0, 0.f), fmaxf(kB1, 0.f));
    }
}

// ---------------- main edge kernel: 2 edges per thread, 3 CTAs/SM ----------------
// dynamic smem layout (floats): sW1[2048] | sW2[4096] | sXs[16*256] | sXv[24*256] | sb1[64] | sb2[128]
#define SMEM_EDGE ((2048 + 4096 + 16 * 256 + 24 * 256 + 64 + 128) * 4)

__global__ void __launch_bounds__(128, 3) edge_kernel(const float* __restrict__ atom,
                                                      const float* __restrict__ efeat,
                                                      const float* __restrict__ esh,
                                                      const int* __restrict__ eidx) {
    extern __shared__ float smem[];
    float* sW1 = smem;            // 2048
    float* sW2 = sW1 + 2048;      // 4096
    float* sXs = sW2 + 4096;      // 4096
    float* sXv = sXs + 4096;      // 6144
    float* sb1 = sXv + 6144;      // 64
    float* sb2 = sb1 + 64;        // 128

    const int tid = threadIdx.x;
    const int eA = blockIdx.x * 256 + tid;
    const int eB = eA + 128;

    for (int i = tid; i < 2048; i += 128) sW1[i] = ((const float*)g_W1T)[i];
    if (tid < 64) sb1[tid] = ((const float*)g_b1)[tid];

    const int dstA = eidx[eA], srcA = eidx[NE + eA];
    const int dstB = eidx[eB], srcB = eidx[NE + eB];
    atomicAdd(&g_count[srcA], 1);
    atomicAdd(&g_count[srcB], 1);

    // stage node features for both edges into smem (feature-major, conflict-free columns)
    {
        const float4* pa = (const float4*)(atom + (size_t)dstA * DD);
        const float4* pb = (const float4*)(atom + (size_t)dstB * DD);
#pragma unroll
        for (int q = 0; q < 4; q++) {
            float4 t = pa[q];
            sXs[(4 * q + 0) * 256 + tid] = t.x; sXs[(4 * q + 1) * 256 + tid] = t.y;
            sXs[(4 * q + 2) * 256 + tid] = t.z; sXs[(4 * q + 3) * 256 + tid] = t.w;
            t = pb[q];
            sXs[(4 * q + 0) * 256 + 128 + tid] = t.x; sXs[(4 * q + 1) * 256 + 128 + tid] = t.y;
            sXs[(4 * q + 2) * 256 + 128 + tid] = t.z; sXs[(4 * q + 3) * 256 + 128 + tid] = t.w;
        }
#pragma unroll
        for (int q = 0; q < 6; q++) {
            float4 t = pa[4 + q];
            sXv[(4 * q + 0) * 256 + tid] = t.x; sXv[(4 * q + 1) * 256 + tid] = t.y;
            sXv[(4 * q + 2) * 256 + tid] = t.z; sXv[(4 * q + 3) * 256 + tid] = t.w;
            t = pb[4 + q];
            sXv[(4 * q + 0) * 256 + 128 + tid] = t.x; sXv[(4 * q + 1) * 256 + 128 + tid] = t.y;
            sXv[(4 * q + 2) * 256 + 128 + tid] = t.z; sXv[(4 * q + 3) * 256 + 128 + tid] = t.w;
        }
    }
    float4 shA = *(const float4*)(esh + (size_t)eA * 4);
    float4 shB = *(const float4*)(esh + (size_t)eB * 4);
    __syncthreads();

    u64 rhA[16], rhB[16];

    // ---- k branch ----
    hidden_branch(efeat, eA, eB, sW1, sb1, rhA, rhB);
    run_branch<0>(rhA, rhB, sXs, sXv,
                  shA.x, shA.y, shA.z, shA.w, shB.x, shB.y, shB.z, shB.w,
                  tid, eA, eB, srcA, srcB, sW2, sb2);

    // ---- v branch (recompute hidden; efeat is L2-resident) ----
    hidden_branch(efeat, eA, eB, sW1 + 1024, sb1 + 32, rhA, rhB);
    run_branch<1>(rhA, rhB, sXs, sXv,
                  shA.x, shA.y, shA.z, shA.w, shB.x, shB.y, shB.z, shB.w,
                  tid, eA, eB, srcA, srcB, sW2, sb2);
}

// ---------------- CSR build: scan ----------------
__global__ void scan_kernel() {
    __shared__ int part[256];
    int tid = threadIdx.x;
    const int CH = (NN + 255) / 256;
    int beg = tid * CH;
    int end = beg + CH < NN ? beg + CH : NN;
    int s = 0;
    for (int i = beg; i < end; i++) s += g_count[i];
    part[tid] = s;
    __syncthreads();
    if (tid == 0) {
        int acc = 0;
        for (int i = 0; i < 256; i++) { int t = part[i]; part[i] = acc; acc += t; }
    }
    __syncthreads();
    int acc = part[tid];
    for (int i = beg; i < end; i++) {
        g_off[i] = acc;
        g_cursor[i] = acc;
        acc += g_count[i];
    }
    if (tid == 255) g_off[NN] = acc;
}

// ---------------- CSR build: scatter ----------------
__global__ void scatter_kernel(const int* __restrict__ eidx) {
    int e = blockIdx.x * 256 + threadIdx.x;
    int src = eidx[NE + e];
    int pos = atomicAdd(&g_cursor[src], 1);
    g_elist[pos] = e;
}

// ---------------- per-node softmax + aggregation + residual + stats ----------------
__global__ void gather_kernel(const float* __restrict__ atom) {
    __shared__ float sacc[48];
    int tid = threadIdx.x;
    if (tid < 48) sacc[tid] = 0.f;
    __syncthreads();
    int lane = tid & 31;
    int n = blockIdx.x * 4 + (tid >> 5);
    float x0 = 0.f, x1 = 0.f;
    {
        int beg = g_off[n], end = g_off[n + 1];
        float m = -INFINITY;
        for (int j = beg + lane; j < end; j += 32) m = fmaxf(m, g_attn[g_elist[j]]);
#pragma unroll
        for (int o = 16; o; o >>= 1) m = fmaxf(m, __shfl_xor_sync(~0u, m, o));
        if (!isfinite(m)) m = 0.f;
        float ds = 0.f;
        for (int j = beg + lane; j < end; j += 32) ds += expf(g_attn[g_elist[j]] - m);
#pragma unroll
        for (int o = 16; o; o >>= 1) ds += __shfl_xor_sync(~0u, ds, o);
        float a0 = 0.f, a1 = 0.f;
        for (int j = beg; j < end; j++) {
            int e = g_elist[j];
            float ev = expf(g_attn[e] - m);
            const float* vp = g_vedge + (size_t)e * DD;
            a0 = fmaf(ev, vp[lane], a0);
            if (lane < 8) a1 = fmaf(ev, vp[32 + lane], a1);
        }
        float inv = (ds != 0.f) ? 1.f / ds : 0.f;
        x0 = atom[(size_t)n * DD + lane] + a0 * inv;
        g_num[(size_t)n * DD + lane] = x0;
        if (lane < 8) {
            x1 = atom[(size_t)n * DD + 32 + lane] + a1 * inv;
            g_num[(size_t)n * DD + 32 + lane] = x1;
        }
    }
    if (lane < 16) {
        atomicAdd(&sacc[lane], x0);
        atomicAdd(&sacc[16 + lane], x0 * x0);
    } else {
        atomicAdd(&sacc[32 + (lane - 16) / 3], x0 * x0);
    }
    if (lane < 8) atomicAdd(&sacc[32 + (lane + 16) / 3], x1 * x1);
    __syncthreads();
    if (tid < 48) atomicAdd(&g_stats[tid], sacc[tid]);
}

// ---------------- finalize: batchnorm + write ----------------
__global__ void finalB_kernel(float* __restrict__ out,
                              const float* __restrict__ ws, const float* __restrict__ bs,
                              const float* __restrict__ wv) {
    int n = blockIdx.x * 256 + threadIdx.x;
    if (n >= NN) return;
    const float invN = 1.f / (float)NN;
#pragma unroll
    for (int c = 0; c < 16; c++) {
        float mu = g_stats[c] * invN;
        float var = g_stats[16 + c] * invN - mu * mu;
        float x = g_num[(size_t)n * DD + c];
        out[(size_t)n * DD + c] = (x - mu) / sqrtf(var + EPSV) * ws[c] + bs[c];
    }
#pragma unroll
    for (int i = 0; i < 8; i++) {
        float norm = g_stats[32 + i] * (invN * (1.f / 3.f));
        float sc = wv[i] / sqrtf(norm + EPSV);
#pragma unroll
        for (int d = 0; d < 3; d++) {
            float x = g_num[(size_t)n * DD + 16 + 3 * i + d];
            out[(size_t)n * DD + 16 + 3 * i + d] = x * sc;
        }
    }
}

// ---------------- launch ----------------
extern "C" void kernel_launch(void* const* d_in, const int* in_sizes, int n_in,
                              void* d_out, int out_size) {
    const float* atom  = (const float*)d_in[0];
    const float* efeat = (const float*)d_in[1];
    const float* esh   = (const float*)d_in[2];
    const float* Wqs   = (const float*)d_in[3];
    const float* Wqv   = (const float*)d_in[4];
    const float* kw1   = (const float*)d_in[5];
    const float* kb1   = (const float*)d_in[6];
    const float* kw2   = (const float*)d_in[7];
    const float* kb2   = (const float*)d_in[8];
    const float* vw1   = (const float*)d_in[9];
    const float* vb1   = (const float*)d_in[10];
    const float* vw2   = (const float*)d_in[11];
    const float* vb2   = (const float*)d_in[12];
    const float* bnws  = (const float*)d_in[13];
    const float* bnbs  = (const float*)d_in[14];
    const float* bnwv  = (const float*)d_in[15];
    const int*   eidx  = (const int*)d_in[16];
    float* out = (float*)d_out;

    cudaFuncSetAttribute(edge_kernel, cudaFuncAttributeMaxDynamicSharedMemorySize, SMEM_EDGE);

    init_kernel<<<(NN + 255) / 256, 256>>>();
    prep_kernel<<<(2 * 22176 + 255) / 256, 256>>>(kw1, kb1, kw2, kb2, vw1, vb1, vw2, vb2);
    qnode_kernel<<<(NN + 255) / 256, 256>>>(atom, Wqs, Wqv);
    edge_kernel<<<NE / 256, 128, SMEM_EDGE>>>(atom, efeat, esh, eidx);
    scan_kernel<<<1, 256>>>();
    scatter_kernel<<<NE / 256, 256>>>(eidx);
    gather_kernel<<<NN / 4, 128>>>(atom);
    finalB_kernel<<<(NN + 255) / 256, 256>>>(out, bnws, bnbs, bnwv);
    cudaMemcpyAsync(out + NN * DD, efeat, (size_t)NE * HE * sizeof(float),
                    cudaMemcpyDeviceToDevice);
}